// round 12
// baseline (speedup 1.0000x reference)
#include <cuda_runtime.h>
#include <cuda_fp16.h>
#include <math.h>
#include <stdint.h>

#define Bb 16
#define Nn 8192
#define Dd 384
#define KN 16
#define KD 8
#define Hh 128
#define STEPS 3
#define M_TOT (Bb*Nn)   // 131072
#define NB 256          // fused weight width (coin 0..127 | path 128..255)

// GEMM: CTA 128 rows x 128 cols, K-chunk 48, 8 chunks, 4-stage pipeline.
#define KC 48
#define NCH 8
#define A_STRIDE 112                 // bytes per A smem row (7 x 16B)
#define A_BYTES (128*A_STRIDE)       // 14336
#define B_STRIDE 272                 // bytes per B smem row (17 x 16B)
#define B_BYTES (KC*B_STRIDE)        // 13056
#define SMBUF (A_BYTES + B_BYTES)    // 27392
#define SM_TOTAL (4*SMBUF)           // 109568 (x2 CTAs = 219KB, co-resident)

// ---- scratch (alloc-free: __device__ globals, fully rewritten every launch) ----
__device__ __half g_Cph[(size_t)M_TOT*Hh]; // path hidden pre-act (sent part)  32MB
__device__ float g_amps[M_TOT*KD];         // coin amplitudes                   4MB
__device__ float g_t[2][M_TOT*KD];         // walk gather arrays              2x4MB
__device__ float g_nsL[M_TOT*KD];          // last step raw ns                  4MB
__device__ float g_qh[2*Bb*Hh];            // per-batch q@W + bias (coin, path)
__device__ float g_part[Bb*128];           // per-block sumsq partials
__device__ __half g_Bh[Dd*NB];             // fused W1, fp16, [k/16][k%16][n]

// ================= helpers =================
__device__ __forceinline__ uint32_t smem_u32(const void* p) {
    uint32_t a;
    asm("{ .reg .u64 t; cvta.to.shared.u64 t, %1; cvt.u32.u64 %0, t; }" : "=r"(a) : "l"(p));
    return a;
}
__device__ __forceinline__ void ldsm4(unsigned &r0, unsigned &r1, unsigned &r2, unsigned &r3,
                                      unsigned addr) {
    asm volatile("ldmatrix.sync.aligned.m8n8.x4.shared.b16 {%0,%1,%2,%3}, [%4];"
                 : "=r"(r0), "=r"(r1), "=r"(r2), "=r"(r3) : "r"(addr));
}
__device__ __forceinline__ void ldsm4t(unsigned &r0, unsigned &r1, unsigned &r2, unsigned &r3,
                                       unsigned addr) {
    asm volatile("ldmatrix.sync.aligned.m8n8.x4.trans.shared.b16 {%0,%1,%2,%3}, [%4];"
                 : "=r"(r0), "=r"(r1), "=r"(r2), "=r"(r3) : "r"(addr));
}
__device__ __forceinline__ void mma16816(float* c, const unsigned* a, unsigned b0, unsigned b1) {
    asm volatile(
        "mma.sync.aligned.m16n8k16.row.col.f32.f16.f16.f32 "
        "{%0,%1,%2,%3}, {%4,%5,%6,%7}, {%8,%9}, {%0,%1,%2,%3};"
        : "+f"(c[0]), "+f"(c[1]), "+f"(c[2]), "+f"(c[3])
        : "r"(a[0]), "r"(a[1]), "r"(a[2]), "r"(a[3]), "r"(b0), "r"(b1));
}
__device__ __forceinline__ uint32_t pack_h2(__half a, __half b) {
    __half2 t; t.x = a; t.y = b;
    return *(uint32_t*)&t;
}
__device__ __forceinline__ void cp16(uint32_t dst, const void* src) {
    asm volatile("cp.async.cg.shared.global [%0], [%1], 16;" :: "r"(dst), "l"(src));
}

// ---------------------------------------------------------------------------
// merged prolog: blocks 0..31 -> qh (b = blk>>1, which = blk&1, 512 thr);
//                blocks 32..223 -> prepB (2 k-rows per block)
// ---------------------------------------------------------------------------
__global__ void prolog_kernel(const float* __restrict__ q,
                              const float* __restrict__ cw1, const float* __restrict__ cb1,
                              const float* __restrict__ pw1, const float* __restrict__ pb1) {
    __shared__ float red[4][Hh];
    int blk = blockIdx.x;
    int tid = threadIdx.x;
    if (blk < 32) {
        int b = blk >> 1, which = blk & 1;
        int h = tid & 127, kc = tid >> 7;
        const float* w1   = which ? pw1 : cw1;
        const float* bias = which ? pb1 : cb1;
        int rowoff = which ? (Dd + KD) : Dd;
        const float* qb = q + b*Dd;
        float acc = 0.f;
        #pragma unroll 4
        for (int k = kc*96; k < kc*96 + 96; k++)
            acc = fmaf(qb[k], w1[(size_t)(rowoff + k)*Hh + h], acc);
        red[kc][h] = acc;
        __syncthreads();
        if (kc == 0)
            g_qh[(which*Bb + b)*Hh + h] = bias[h] + ((red[0][h] + red[1][h])
                                                  +  (red[2][h] + red[3][h]));
    } else {
        int idx = (blk - 32)*512 + tid;       // 192 blocks * 512 = 98304
        int k = idx >> 8, n = idx & 255;
        const float* w = (n < Hh) ? cw1 : pw1;
        float v = w[(size_t)k*Hh + (n & (Hh-1))];
        g_Bh[(k >> 4)*(16*NB) + (k & 15)*NB + n] = __float2half_rn(v);
    }
}

// ---------------------------------------------------------------------------
// HMMA GEMM: CTA = 128 rows x 128 cols (which = bid&1: 0 coin, 1 path),
// K=384 in 8 chunks of 48, fp16 single pass, fp32 accum.
// 4-stage smem pipeline; B via cp.async (depth ~2-3 chunks); A via coalesced
// flat-unit LDG. 8 warps = 4(M) x 2(N), 2 CTAs/SM.
// ---------------------------------------------------------------------------
__global__ void __launch_bounds__(256, 2)
gemm_hmma(const float* __restrict__ A,
          const float* __restrict__ cw2, const float* __restrict__ cb2) {
    extern __shared__ char smem[];
    const uint32_t sbase = smem_u32(smem);
    const int tid = threadIdx.x, lane = tid & 31, wid = tid >> 5;
    const int wm = wid >> 1, wn = wid & 1;
    const int which = blockIdx.x & 1;
    const size_t row0 = (size_t)(blockIdx.x >> 1) * 128;

    float c[2][8][4];
    #pragma unroll
    for (int i = 0; i < 2; i++)
        #pragma unroll
        for (int j = 0; j < 8; j++)
            #pragma unroll
            for (int l = 0; l < 4; l++) c[i][j][l] = 0.f;

    // A: flat-unit mapping. Chunk = 128 rows x 48 floats = 1536 x 16B units.
    uint32_t a_goff[6];   // gmem float offset within row-block
    uint32_t a_soff[6];   // smem byte offset (fp16)
    #pragma unroll
    for (int i = 0; i < 6; i++) {
        int u = tid + 256*i;
        int r = u / 12, cc = u % 12;
        a_goff[i] = (uint32_t)r*Dd + (uint32_t)cc*4;
        a_soff[i] = (uint32_t)r*A_STRIDE + (uint32_t)cc*8;
    }
    const float* Abase = A + row0*Dd;
    // B: thread -> rows {brow, brow+16, brow+32}, 8 halves at bn8
    const int brow = tid >> 4, bn8 = (tid & 15)*8;
    const int b_src0 = brow*NB + which*Hh + bn8;
    const uint32_t b_sts0 = A_BYTES + (uint32_t)brow*B_STRIDE + (uint32_t)bn8*2;

    // ldmatrix lane offsets
    const uint32_t a_lane = (uint32_t)(lane & 15)*A_STRIDE + (uint32_t)(lane >> 4)*16;
    const uint32_t b_lane = (uint32_t)((lane & 7) + ((lane >> 3) & 1)*8)*B_STRIDE
                          + (uint32_t)(wn*64 + (lane >> 4)*8)*2;

    float4 areg[6];

    #define LDG_A(ch) do {                                                     \
        _Pragma("unroll")                                                      \
        for (int _i = 0; _i < 6; _i++)                                         \
            areg[_i] = *(const float4*)(Abase + (ch)*KC + a_goff[_i]);         \
    } while (0)

    #define STS_A(bufbyte) do {                                               \
        char* _bc = smem + (bufbyte);                                          \
        _Pragma("unroll")                                                      \
        for (int _i = 0; _i < 6; _i++) {                                       \
            uint32_t _lo = pack_h2(__float2half_rn(areg[_i].x),                \
                                   __float2half_rn(areg[_i].y));               \
            uint32_t _hi = pack_h2(__float2half_rn(areg[_i].z),                \
                                   __float2half_rn(areg[_i].w));               \
            *(uint2*)(_bc + a_soff[_i]) = make_uint2(_lo, _hi);                \
        }                                                                      \
    } while (0)

    #define CP_B(ch, bufbyte) do {                                            \
        _Pragma("unroll")                                                      \
        for (int _j = 0; _j < 3; _j++)                                         \
            cp16(sbase + (bufbyte) + b_sts0 + (uint32_t)_j*16*B_STRIDE,        \
                 g_Bh + ((ch)*3 + _j)*4096 + b_src0);                          \
        asm volatile("cp.async.commit_group;" ::: "memory");                   \
    } while (0)

    // prologue: B chunks 0..2 in flight, A chunk 0 staged
    LDG_A(0);
    CP_B(0, 0);
    CP_B(1, SMBUF);
    CP_B(2, 2*SMBUF);
    STS_A(0);
    asm volatile("cp.async.wait_group 2;" ::: "memory");
    __syncthreads();

    for (int ch = 0; ch < NCH; ch++) {
        const uint32_t bufc = (uint32_t)(ch % 4)*SMBUF;
        if (ch + 1 < NCH) LDG_A(ch + 1);
        // ---- MMA on buffer cur ----
        {
            const uint32_t sb0 = sbase + bufc;
            #pragma unroll
            for (int s = 0; s < 3; s++) {
                unsigned af[2][4];
                #pragma unroll
                for (int rg = 0; rg < 2; rg++)
                    ldsm4(af[rg][0], af[rg][1], af[rg][2], af[rg][3],
                          sb0 + (uint32_t)((wm*32 + rg*16)*A_STRIDE) + a_lane
                              + (uint32_t)s*32);
                #pragma unroll
                for (int pr = 0; pr < 4; pr++) {
                    unsigned b0, b1, b2_, b3;
                    ldsm4t(b0, b1, b2_, b3,
                           sb0 + A_BYTES + (uint32_t)s*(16*B_STRIDE)
                               + (uint32_t)pr*32 + b_lane);
                    #pragma unroll
                    for (int rg = 0; rg < 2; rg++) {
                        mma16816(c[rg][2*pr],     af[rg], b0,  b1);
                        mma16816(c[rg][2*pr + 1], af[rg], b2_, b3);
                    }
                }
            }
        }
        if (ch + 1 < NCH) STS_A((uint32_t)((ch + 1) % 4)*SMBUF);
        if (ch + 3 < NCH) {
            CP_B(ch + 3, (uint32_t)((ch + 3) % 4)*SMBUF);
            asm volatile("cp.async.wait_group 2;" ::: "memory");
        } else if (ch + 2 < NCH) {
            asm volatile("cp.async.wait_group 1;" ::: "memory");
        } else if (ch + 1 < NCH) {
            asm volatile("cp.async.wait_group 0;" ::: "memory");
        }
        __syncthreads();
    }

    const int gr = lane >> 2, gq = lane & 3, gc2 = gq*2;

    if (which == 1) {
        // path: store pre-act to g_Cph as fp16
        #pragma unroll
        for (int rg = 0; rg < 2; rg++)
            #pragma unroll
            for (int ng = 0; ng < 8; ng++) {
                int r = wm*32 + rg*16 + gr;
                int pcol = wn*64 + ng*8 + gc2;
                *(__half2*)&g_Cph[(row0 + r)*Hh + pcol] =
                    __floats2half2_rn(c[rg][ng][0], c[rg][ng][1]);
                *(__half2*)&g_Cph[(row0 + r + 8)*Hh + pcol] =
                    __floats2half2_rn(c[rg][ng][2], c[rg][ng][3]);
            }
        return;
    }

    // ---- coin epilogue: layer-2 via quad-shuffle partials ----
    const int b = blockIdx.x >> 7;            // 64 tiles * 2 per batch
    float* part = (float*)smem;               // [128][2][8]
    float* w2s  = (float*)(smem + 8192);      // [128*8]
    float* qhs  = (float*)(smem + 12288);     // [128]
    float* b2s  = (float*)(smem + 12800);     // [8]
    for (int i = tid; i < Hh*KD; i += 256) w2s[i] = cw2[i];
    if (tid < Hh) qhs[tid] = g_qh[b*Hh + tid];
    if (tid < KD) b2s[tid] = cb2[tid];
    __syncthreads();

    #pragma unroll
    for (int rg = 0; rg < 2; rg++) {
        float pa[8], pb[8];
        #pragma unroll
        for (int j = 0; j < 8; j++) { pa[j] = 0.f; pb[j] = 0.f; }
        #pragma unroll
        for (int ng = 0; ng < 8; ng++) {
            int col = wn*64 + ng*8 + gc2;
            float qa = qhs[col], qb = qhs[col + 1];
            float h0 = fmaxf(c[rg][ng][0] + qa, 0.f);
            float h1 = fmaxf(c[rg][ng][1] + qb, 0.f);
            float h2 = fmaxf(c[rg][ng][2] + qa, 0.f);
            float h3 = fmaxf(c[rg][ng][3] + qb, 0.f);
            #pragma unroll
            for (int j = 0; j < 8; j++) {
                float w0 = w2s[col*8 + j], w1 = w2s[(col + 1)*8 + j];
                pa[j] += h0*w0 + h1*w1;
                pb[j] += h2*w0 + h3*w1;
            }
        }
        #pragma unroll
        for (int j = 0; j < 8; j++) {
            pa[j] += __shfl_xor_sync(0xffffffffu, pa[j], 1);
            pa[j] += __shfl_xor_sync(0xffffffffu, pa[j], 2);
            pb[j] += __shfl_xor_sync(0xffffffffu, pb[j], 1);
            pb[j] += __shfl_xor_sync(0xffffffffu, pb[j], 2);
        }
        if (gq == 0) {
            int row = wm*32 + rg*16 + gr;
            #pragma unroll
            for (int j = 0; j < 8; j++) {
                part[(row*2 + wn)*8 + j]       = pa[j];
                part[((row + 8)*2 + wn)*8 + j] = pb[j];
            }
        }
    }
    __syncthreads();

    #pragma unroll
    for (int it = 0; it < 4; it++) {
        int idx = it*256 + tid;
        int row = idx >> 3, j = idx & 7;
        float acc = b2s[j] + part[(row*2)*8 + j] + part[(row*2 + 1)*8 + j];
        g_amps[(row0 + row)*KD + j] = acc;
        g_t[0][(row0 + row)*KD + j] = acc * 0.00390625f;
    }
}

// ---------------------------------------------------------------------------
// One walk step. 128 threads = 64 nodes x 2 k-halves; 2048 blocks.
// Warp-level coef; 2 barriers total.
// ---------------------------------------------------------------------------
__global__ void walk_kernel(const int* __restrict__ nbrs, int step) {
    __shared__ int   nb[64*KN];
    __shared__ float red[4];
    int b  = blockIdx.y;
    int n0 = blockIdx.x * 64;
    int tid = threadIdx.x, lane = tid & 31, wid = tid >> 5;

    const int4* nb_g = (const int4*)(nbrs + ((size_t)(b*Nn + n0))*KN);
    int4* nb4 = (int4*)nb;
    nb4[tid]       = nb_g[tid];
    nb4[tid + 128] = nb_g[tid + 128];

    float coef = 1.0f;
    if (step > 0) {
        float p = (g_part[b*128 + lane]      + g_part[b*128 + 32 + lane])
                + (g_part[b*128 + 64 + lane] + g_part[b*128 + 96 + lane]);
        #pragma unroll
        for (int m = 16; m > 0; m >>= 1) p += __shfl_xor_sync(0xffffffffu, p, m);
        coef = (p > 0.f) ? rsqrtf(p) : 1.0f;
    }
    __syncthreads();

    int node = tid >> 1, kh = (tid & 1)*4;
    int n = n0 + node;
    const float* tb = g_t[step & 1] + (size_t)b*Nn*KD;

    float4 acc = *(const float4*)(tb + n*KD + kh);
    #pragma unroll
    for (int j = 0; j < KN; j++) {
        int idx = nb[node*KN + j];
        if (idx >= 0 && idx < Nn) {
            float4 v = *(const float4*)(tb + idx*KD + kh);
            acc.x += v.x; acc.y += v.y; acc.z += v.z; acc.w += v.w;
        }
    }
    float4 ns = make_float4(coef*acc.x, coef*acc.y, coef*acc.z, coef*acc.w);

    size_t gi = ((size_t)b*Nn + n)*KD + kh;
    if (step < STEPS - 1) {
        float4 am = *(const float4*)(g_amps + gi);
        *(float4*)(g_t[(step + 1) & 1] + gi) =
            make_float4(ns.x*am.x, ns.y*am.y, ns.z*am.z, ns.w*am.w);
    } else {
        *(float4*)(g_nsL + gi) = ns;
    }

    float s = ns.x*ns.x + ns.y*ns.y + ns.z*ns.z + ns.w*ns.w;
    #pragma unroll
    for (int m = 16; m > 0; m >>= 1) s += __shfl_xor_sync(0xffffffffu, s, m);
    if (lane == 0) red[wid] = s;
    __syncthreads();
    if (tid == 0)
        g_part[b*128 + blockIdx.x] = (red[0] + red[1]) + (red[2] + red[3]);
}

// ---------------------------------------------------------------------------
// Final path MLP. Warp-level coef; Cp read as fp16.
// ---------------------------------------------------------------------------
__global__ void final_kernel(const float* __restrict__ pw1,
                             const float* __restrict__ w2, const float* __restrict__ b2,
                             float* __restrict__ out) {
    __shared__ float wst[KD*Hh];
    __shared__ float w2s[Hh];
    int tid = threadIdx.x, lane = tid & 31;
    int b = blockIdx.x >> 10;   // 1024 blocks per batch

    for (int i = tid; i < KD*Hh; i += 256) wst[i] = pw1[(size_t)Dd*Hh + i];
    if (tid < Hh) w2s[tid] = w2[tid];

    float p = (g_part[b*128 + lane]      + g_part[b*128 + 32 + lane])
            + (g_part[b*128 + 64 + lane] + g_part[b*128 + 96 + lane]);
    #pragma unroll
    for (int m = 16; m > 0; m >>= 1) p += __shfl_xor_sync(0xffffffffu, p, m);
    float inv = (p > 0.f) ? rsqrtf(p) : 1.0f;
    __syncthreads();

    int r = blockIdx.x*8 + (tid >> 5);
    int l = lane;

    const float* nsf = g_nsL + (size_t)r*KD;
    float s[KD];
    #pragma unroll
    for (int k = 0; k < KD; k++) s[k] = nsf[k] * inv;

    uint2 raw = *(const uint2*)&g_Cph[(size_t)r*Hh + l*4];
    float2 c01 = __half22float2(*(__half2*)&raw.x);
    float2 c23 = __half22float2(*(__half2*)&raw.y);
    float4 qv = *(const float4*)&g_qh[(Bb + b)*Hh + l*4];
    float hv[4] = { c01.x+qv.x, c01.y+qv.y, c23.x+qv.z, c23.y+qv.w };
    #pragma unroll
    for (int k = 0; k < KD; k++)
        #pragma unroll
        for (int i = 0; i < 4; i++)
            hv[i] = fmaf(s[k], wst[k*Hh + l*4 + i], hv[i]);

    float part = 0.f;
    #pragma unroll
    for (int i = 0; i < 4; i++) {
        float h = fmaxf(hv[i], 0.f);
        part = fmaf(h, w2s[l*4 + i], part);
    }
    #pragma unroll
    for (int m = 16; m > 0; m >>= 1)
        part += __shfl_xor_sync(0xffffffffu, part, m);
    if (l == 0) out[r] = part + b2[0];
}

// ---------------------------------------------------------------------------
extern "C" void kernel_launch(void* const* d_in, const int* in_sizes, int n_in,
                              void* d_out, int out_size) {
    const float* sent = (const float*)d_in[0];
    const float* q    = (const float*)d_in[1];
    const int*   nbrs = (const int*)  d_in[2];
    const float* cw1  = (const float*)d_in[3];
    const float* cb1  = (const float*)d_in[4];
    const float* cw2  = (const float*)d_in[5];
    const float* cb2  = (const float*)d_in[6];
    const float* pw1  = (const float*)d_in[7];
    const float* pb1  = (const float*)d_in[8];
    const float* pw2  = (const float*)d_in[9];
    const float* pb2  = (const float*)d_in[10];
    float* out = (float*)d_out;

    cudaFuncSetAttribute(gemm_hmma, cudaFuncAttributeMaxDynamicSharedMemorySize, SM_TOTAL);

    prolog_kernel<<<224, 512>>>(q, cw1, cb1, pw1, pb1);
    gemm_hmma<<<(M_TOT/128)*2, 256, SM_TOTAL>>>(sent, cw2, cb2);
    for (int s = 0; s < STEPS; s++)
        walk_kernel<<<dim3(Nn/64, Bb), 128>>>(nbrs, s);
    final_kernel<<<M_TOT/8, 256>>>(pw1, pw2, pb2, out);
}

// round 13
// speedup vs baseline: 1.1848x; 1.1848x over previous
#include <cuda_runtime.h>
#include <cuda_fp16.h>
#include <math.h>
#include <stdint.h>

#define Bb 16
#define Nn 8192
#define Dd 384
#define KN 16
#define KD 8
#define Hh 128
#define STEPS 3
#define M_TOT (Bb*Nn)   // 131072
#define NB 256          // fused weight width (coin 0..127 | path 128..255)

// GEMM: CTA 128 rows x 128 cols, K-chunk 48, 8 chunks, 3-stage pipeline (R11).
#define KC 48
#define NCH 8
#define A_STRIDE 112                 // bytes per A smem row (7 x 16B)
#define A_BYTES (128*A_STRIDE)       // 14336
#define B_STRIDE 272                 // bytes per B smem row (17 x 16B)
#define B_BYTES (KC*B_STRIDE)        // 13056
#define SMBUF (A_BYTES + B_BYTES)    // 27392
#define SM_TOTAL (3*SMBUF)           // 82176  (x2 CTAs = 164KB, co-resident)

// ---- scratch (alloc-free: __device__ globals, fully rewritten every launch) ----
__device__ __half g_Cph[(size_t)M_TOT*Hh]; // path hidden pre-act (sent part)  32MB
__device__ float g_amps[M_TOT*KD];         // coin amplitudes                   4MB
__device__ float g_t[2][M_TOT*KD];         // walk gather arrays              2x4MB
__device__ float g_nsL[M_TOT*KD];          // last step raw ns                  4MB
__device__ float g_qh[2*Bb*Hh];            // per-batch q@W + bias (coin, path)
__device__ float g_part[Bb*128];           // per-block sumsq partials
__device__ __half g_Bh[Dd*NB];             // fused W1, fp16, [k/16][k%16][n]

// ================= helpers =================
__device__ __forceinline__ uint32_t smem_u32(const void* p) {
    uint32_t a;
    asm("{ .reg .u64 t; cvta.to.shared.u64 t, %1; cvt.u32.u64 %0, t; }" : "=r"(a) : "l"(p));
    return a;
}
__device__ __forceinline__ void ldsm4(unsigned &r0, unsigned &r1, unsigned &r2, unsigned &r3,
                                      unsigned addr) {
    asm volatile("ldmatrix.sync.aligned.m8n8.x4.shared.b16 {%0,%1,%2,%3}, [%4];"
                 : "=r"(r0), "=r"(r1), "=r"(r2), "=r"(r3) : "r"(addr));
}
__device__ __forceinline__ void ldsm4t(unsigned &r0, unsigned &r1, unsigned &r2, unsigned &r3,
                                       unsigned addr) {
    asm volatile("ldmatrix.sync.aligned.m8n8.x4.trans.shared.b16 {%0,%1,%2,%3}, [%4];"
                 : "=r"(r0), "=r"(r1), "=r"(r2), "=r"(r3) : "r"(addr));
}
__device__ __forceinline__ void mma16816(float* c, const unsigned* a, unsigned b0, unsigned b1) {
    asm volatile(
        "mma.sync.aligned.m16n8k16.row.col.f32.f16.f16.f32 "
        "{%0,%1,%2,%3}, {%4,%5,%6,%7}, {%8,%9}, {%0,%1,%2,%3};"
        : "+f"(c[0]), "+f"(c[1]), "+f"(c[2]), "+f"(c[3])
        : "r"(a[0]), "r"(a[1]), "r"(a[2]), "r"(a[3]), "r"(b0), "r"(b1));
}
__device__ __forceinline__ uint32_t pack_h2(__half a, __half b) {
    __half2 t; t.x = a; t.y = b;
    return *(uint32_t*)&t;
}
__device__ __forceinline__ void cp16(uint32_t dst, const void* src) {
    asm volatile("cp.async.cg.shared.global [%0], [%1], 16;" :: "r"(dst), "l"(src));
}

// ---------------------------------------------------------------------------
// merged prolog: blocks 0..31 -> qh (b = blk>>1, which = blk&1, 512 thr);
//                blocks 32..223 -> prepB (2 k-rows per block)
// ---------------------------------------------------------------------------
__global__ void prolog_kernel(const float* __restrict__ q,
                              const float* __restrict__ cw1, const float* __restrict__ cb1,
                              const float* __restrict__ pw1, const float* __restrict__ pb1) {
    __shared__ float red[4][Hh];
    int blk = blockIdx.x;
    int tid = threadIdx.x;
    if (blk < 32) {
        int b = blk >> 1, which = blk & 1;
        int h = tid & 127, kc = tid >> 7;
        const float* w1   = which ? pw1 : cw1;
        const float* bias = which ? pb1 : cb1;
        int rowoff = which ? (Dd + KD) : Dd;
        const float* qb = q + b*Dd;
        float acc = 0.f;
        #pragma unroll 4
        for (int k = kc*96; k < kc*96 + 96; k++)
            acc = fmaf(qb[k], w1[(size_t)(rowoff + k)*Hh + h], acc);
        red[kc][h] = acc;
        __syncthreads();
        if (kc == 0)
            g_qh[(which*Bb + b)*Hh + h] = bias[h] + ((red[0][h] + red[1][h])
                                                  +  (red[2][h] + red[3][h]));
    } else {
        int idx = (blk - 32)*512 + tid;       // 192 blocks * 512 = 98304
        int k = idx >> 8, n = idx & 255;
        const float* w = (n < Hh) ? cw1 : pw1;
        float v = w[(size_t)k*Hh + (n & (Hh-1))];
        g_Bh[(k >> 4)*(16*NB) + (k & 15)*NB + n] = __float2half_rn(v);
    }
}

// ---------------------------------------------------------------------------
// HMMA GEMM (R11 config): CTA = 128 rows x 128 cols (which = bid&1),
// K=384 in 8 chunks of 48, fp16 single pass, fp32 accum.
// 3-stage smem pipeline; B via cp.async; A via coalesced flat-unit LDG.
// 8 warps = 4(M) x 2(N), 2 CTAs/SM. Path output stored fp16.
// ---------------------------------------------------------------------------
__global__ void __launch_bounds__(256, 2)
gemm_hmma(const float* __restrict__ A,
          const float* __restrict__ cw2, const float* __restrict__ cb2) {
    extern __shared__ char smem[];
    const uint32_t sbase = smem_u32(smem);
    const int tid = threadIdx.x, lane = tid & 31, wid = tid >> 5;
    const int wm = wid >> 1, wn = wid & 1;
    const int which = blockIdx.x & 1;
    const size_t row0 = (size_t)(blockIdx.x >> 1) * 128;

    float c[2][8][4];
    #pragma unroll
    for (int i = 0; i < 2; i++)
        #pragma unroll
        for (int j = 0; j < 8; j++)
            #pragma unroll
            for (int l = 0; l < 4; l++) c[i][j][l] = 0.f;

    // A: flat-unit mapping. Chunk = 128 rows x 48 floats = 1536 x 16B units.
    uint32_t a_goff[6];   // gmem float offset within row-block
    uint32_t a_soff[6];   // smem byte offset (fp16)
    #pragma unroll
    for (int i = 0; i < 6; i++) {
        int u = tid + 256*i;
        int r = u / 12, cc = u % 12;
        a_goff[i] = (uint32_t)r*Dd + (uint32_t)cc*4;
        a_soff[i] = (uint32_t)r*A_STRIDE + (uint32_t)cc*8;
    }
    const float* Abase = A + row0*Dd;
    // B: thread -> rows {brow, brow+16, brow+32}, 8 halves at bn8
    const int brow = tid >> 4, bn8 = (tid & 15)*8;
    const int b_src0 = brow*NB + which*Hh + bn8;
    const uint32_t b_sts0 = A_BYTES + (uint32_t)brow*B_STRIDE + (uint32_t)bn8*2;

    // ldmatrix lane offsets
    const uint32_t a_lane = (uint32_t)(lane & 15)*A_STRIDE + (uint32_t)(lane >> 4)*16;
    const uint32_t b_lane = (uint32_t)((lane & 7) + ((lane >> 3) & 1)*8)*B_STRIDE
                          + (uint32_t)(wn*64 + (lane >> 4)*8)*2;

    float4 areg[6];

    #define LDG_A(ch) do {                                                     \
        _Pragma("unroll")                                                      \
        for (int _i = 0; _i < 6; _i++)                                         \
            areg[_i] = *(const float4*)(Abase + (ch)*KC + a_goff[_i]);         \
    } while (0)

    #define STS_A(bufbyte) do {                                               \
        char* _bc = smem + (bufbyte);                                          \
        _Pragma("unroll")                                                      \
        for (int _i = 0; _i < 6; _i++) {                                       \
            uint32_t _lo = pack_h2(__float2half_rn(areg[_i].x),                \
                                   __float2half_rn(areg[_i].y));               \
            uint32_t _hi = pack_h2(__float2half_rn(areg[_i].z),                \
                                   __float2half_rn(areg[_i].w));               \
            *(uint2*)(_bc + a_soff[_i]) = make_uint2(_lo, _hi);                \
        }                                                                      \
    } while (0)

    #define CP_B(ch, bufbyte) do {                                            \
        _Pragma("unroll")                                                      \
        for (int _j = 0; _j < 3; _j++)                                         \
            cp16(sbase + (bufbyte) + b_sts0 + (uint32_t)_j*16*B_STRIDE,        \
                 g_Bh + ((ch)*3 + _j)*4096 + b_src0);                          \
        asm volatile("cp.async.commit_group;" ::: "memory");                   \
    } while (0)

    // prologue: buf0 <- chunk0, buf1 <- B(1) in flight
    LDG_A(0);
    CP_B(0, 0);
    CP_B(1, SMBUF);
    STS_A(0);
    asm volatile("cp.async.wait_group 1;" ::: "memory");
    __syncthreads();

    for (int ch = 0; ch < NCH; ch++) {
        const uint32_t bufc = (uint32_t)(ch % 3)*SMBUF;
        if (ch + 1 < NCH) LDG_A(ch + 1);
        // ---- MMA on buffer cur ----
        {
            const uint32_t sb0 = sbase + bufc;
            #pragma unroll
            for (int s = 0; s < 3; s++) {
                unsigned af[2][4];
                #pragma unroll
                for (int rg = 0; rg < 2; rg++)
                    ldsm4(af[rg][0], af[rg][1], af[rg][2], af[rg][3],
                          sb0 + (uint32_t)((wm*32 + rg*16)*A_STRIDE) + a_lane
                              + (uint32_t)s*32);
                #pragma unroll
                for (int pr = 0; pr < 4; pr++) {
                    unsigned b0, b1, b2_, b3;
                    ldsm4t(b0, b1, b2_, b3,
                           sb0 + A_BYTES + (uint32_t)s*(16*B_STRIDE)
                               + (uint32_t)pr*32 + b_lane);
                    #pragma unroll
                    for (int rg = 0; rg < 2; rg++) {
                        mma16816(c[rg][2*pr],     af[rg], b0,  b1);
                        mma16816(c[rg][2*pr + 1], af[rg], b2_, b3);
                    }
                }
            }
        }
        if (ch + 1 < NCH) STS_A((uint32_t)((ch + 1) % 3)*SMBUF);
        if (ch + 2 < NCH) {
            CP_B(ch + 2, (uint32_t)((ch + 2) % 3)*SMBUF);
            asm volatile("cp.async.wait_group 1;" ::: "memory");
        } else {
            asm volatile("cp.async.wait_group 0;" ::: "memory");
        }
        __syncthreads();
    }

    const int gr = lane >> 2, gq = lane & 3, gc2 = gq*2;

    if (which == 1) {
        // path: store pre-act to g_Cph as fp16
        #pragma unroll
        for (int rg = 0; rg < 2; rg++)
            #pragma unroll
            for (int ng = 0; ng < 8; ng++) {
                int r = wm*32 + rg*16 + gr;
                int pcol = wn*64 + ng*8 + gc2;
                *(__half2*)&g_Cph[(row0 + r)*Hh + pcol] =
                    __floats2half2_rn(c[rg][ng][0], c[rg][ng][1]);
                *(__half2*)&g_Cph[(row0 + r + 8)*Hh + pcol] =
                    __floats2half2_rn(c[rg][ng][2], c[rg][ng][3]);
            }
        return;
    }

    // ---- coin epilogue: layer-2 via quad-shuffle partials ----
    const int b = blockIdx.x >> 7;            // 64 tiles * 2 per batch
    float* part = (float*)smem;               // [128][2][8]
    float* w2s  = (float*)(smem + 8192);      // [128*8]
    float* qhs  = (float*)(smem + 12288);     // [128]
    float* b2s  = (float*)(smem + 12800);     // [8]
    for (int i = tid; i < Hh*KD; i += 256) w2s[i] = cw2[i];
    if (tid < Hh) qhs[tid] = g_qh[b*Hh + tid];
    if (tid < KD) b2s[tid] = cb2[tid];
    __syncthreads();

    #pragma unroll
    for (int rg = 0; rg < 2; rg++) {
        float pa[8], pb[8];
        #pragma unroll
        for (int j = 0; j < 8; j++) { pa[j] = 0.f; pb[j] = 0.f; }
        #pragma unroll
        for (int ng = 0; ng < 8; ng++) {
            int col = wn*64 + ng*8 + gc2;
            float qa = qhs[col], qb = qhs[col + 1];
            float h0 = fmaxf(c[rg][ng][0] + qa, 0.f);
            float h1 = fmaxf(c[rg][ng][1] + qb, 0.f);
            float h2 = fmaxf(c[rg][ng][2] + qa, 0.f);
            float h3 = fmaxf(c[rg][ng][3] + qb, 0.f);
            #pragma unroll
            for (int j = 0; j < 8; j++) {
                float w0 = w2s[col*8 + j], w1 = w2s[(col + 1)*8 + j];
                pa[j] += h0*w0 + h1*w1;
                pb[j] += h2*w0 + h3*w1;
            }
        }
        #pragma unroll
        for (int j = 0; j < 8; j++) {
            pa[j] += __shfl_xor_sync(0xffffffffu, pa[j], 1);
            pa[j] += __shfl_xor_sync(0xffffffffu, pa[j], 2);
            pb[j] += __shfl_xor_sync(0xffffffffu, pb[j], 1);
            pb[j] += __shfl_xor_sync(0xffffffffu, pb[j], 2);
        }
        if (gq == 0) {
            int row = wm*32 + rg*16 + gr;
            #pragma unroll
            for (int j = 0; j < 8; j++) {
                part[(row*2 + wn)*8 + j]       = pa[j];
                part[((row + 8)*2 + wn)*8 + j] = pb[j];
            }
        }
    }
    __syncthreads();

    #pragma unroll
    for (int it = 0; it < 4; it++) {
        int idx = it*256 + tid;
        int row = idx >> 3, j = idx & 7;
        float acc = b2s[j] + part[(row*2)*8 + j] + part[(row*2 + 1)*8 + j];
        g_amps[(row0 + row)*KD + j] = acc;
        g_t[0][(row0 + row)*KD + j] = acc * 0.00390625f;
    }
}

// ---------------------------------------------------------------------------
// One walk step. 128 threads = 64 nodes x 2 k-halves; 2048 blocks.
// Warp-level coef; 2 barriers total.
// ---------------------------------------------------------------------------
__global__ void walk_kernel(const int* __restrict__ nbrs, int step) {
    __shared__ int   nb[64*KN];
    __shared__ float red[4];
    int b  = blockIdx.y;
    int n0 = blockIdx.x * 64;
    int tid = threadIdx.x, lane = tid & 31, wid = tid >> 5;

    const int4* nb_g = (const int4*)(nbrs + ((size_t)(b*Nn + n0))*KN);
    int4* nb4 = (int4*)nb;
    nb4[tid]       = nb_g[tid];
    nb4[tid + 128] = nb_g[tid + 128];

    float coef = 1.0f;
    if (step > 0) {
        float p = (g_part[b*128 + lane]      + g_part[b*128 + 32 + lane])
                + (g_part[b*128 + 64 + lane] + g_part[b*128 + 96 + lane]);
        #pragma unroll
        for (int m = 16; m > 0; m >>= 1) p += __shfl_xor_sync(0xffffffffu, p, m);
        coef = (p > 0.f) ? rsqrtf(p) : 1.0f;
    }
    __syncthreads();

    int node = tid >> 1, kh = (tid & 1)*4;
    int n = n0 + node;
    const float* tb = g_t[step & 1] + (size_t)b*Nn*KD;

    float4 acc = *(const float4*)(tb + n*KD + kh);
    #pragma unroll
    for (int j = 0; j < KN; j++) {
        int idx = nb[node*KN + j];
        if (idx >= 0 && idx < Nn) {
            float4 v = *(const float4*)(tb + idx*KD + kh);
            acc.x += v.x; acc.y += v.y; acc.z += v.z; acc.w += v.w;
        }
    }
    float4 ns = make_float4(coef*acc.x, coef*acc.y, coef*acc.z, coef*acc.w);

    size_t gi = ((size_t)b*Nn + n)*KD + kh;
    if (step < STEPS - 1) {
        float4 am = *(const float4*)(g_amps + gi);
        *(float4*)(g_t[(step + 1) & 1] + gi) =
            make_float4(ns.x*am.x, ns.y*am.y, ns.z*am.z, ns.w*am.w);
    } else {
        *(float4*)(g_nsL + gi) = ns;
    }

    float s = ns.x*ns.x + ns.y*ns.y + ns.z*ns.z + ns.w*ns.w;
    #pragma unroll
    for (int m = 16; m > 0; m >>= 1) s += __shfl_xor_sync(0xffffffffu, s, m);
    if (lane == 0) red[wid] = s;
    __syncthreads();
    if (tid == 0)
        g_part[b*128 + blockIdx.x] = (red[0] + red[1]) + (red[2] + red[3]);
}

// ---------------------------------------------------------------------------
// Final path MLP. Warp-level coef; Cp read as fp16.
// ---------------------------------------------------------------------------
__global__ void final_kernel(const float* __restrict__ pw1,
                             const float* __restrict__ w2, const float* __restrict__ b2,
                             float* __restrict__ out) {
    __shared__ float wst[KD*Hh];
    __shared__ float w2s[Hh];
    int tid = threadIdx.x, lane = tid & 31;
    int b = blockIdx.x >> 10;   // 1024 blocks per batch

    for (int i = tid; i < KD*Hh; i += 256) wst[i] = pw1[(size_t)Dd*Hh + i];
    if (tid < Hh) w2s[tid] = w2[tid];

    float p = (g_part[b*128 + lane]      + g_part[b*128 + 32 + lane])
            + (g_part[b*128 + 64 + lane] + g_part[b*128 + 96 + lane]);
    #pragma unroll
    for (int m = 16; m > 0; m >>= 1) p += __shfl_xor_sync(0xffffffffu, p, m);
    float inv = (p > 0.f) ? rsqrtf(p) : 1.0f;
    __syncthreads();

    int r = blockIdx.x*8 + (tid >> 5);
    int l = lane;

    const float* nsf = g_nsL + (size_t)r*KD;
    float s[KD];
    #pragma unroll
    for (int k = 0; k < KD; k++) s[k] = nsf[k] * inv;

    uint2 raw = *(const uint2*)&g_Cph[(size_t)r*Hh + l*4];
    float2 c01 = __half22float2(*(__half2*)&raw.x);
    float2 c23 = __half22float2(*(__half2*)&raw.y);
    float4 qv = *(const float4*)&g_qh[(Bb + b)*Hh + l*4];
    float hv[4] = { c01.x+qv.x, c01.y+qv.y, c23.x+qv.z, c23.y+qv.w };
    #pragma unroll
    for (int k = 0; k < KD; k++)
        #pragma unroll
        for (int i = 0; i < 4; i++)
            hv[i] = fmaf(s[k], wst[k*Hh + l*4 + i], hv[i]);

    float part = 0.f;
    #pragma unroll
    for (int i = 0; i < 4; i++) {
        float h = fmaxf(hv[i], 0.f);
        part = fmaf(h, w2s[l*4 + i], part);
    }
    #pragma unroll
    for (int m = 16; m > 0; m >>= 1)
        part += __shfl_xor_sync(0xffffffffu, part, m);
    if (l == 0) out[r] = part + b2[0];
}

// ---------------------------------------------------------------------------
extern "C" void kernel_launch(void* const* d_in, const int* in_sizes, int n_in,
                              void* d_out, int out_size) {
    const float* sent = (const float*)d_in[0];
    const float* q    = (const float*)d_in[1];
    const int*   nbrs = (const int*)  d_in[2];
    const float* cw1  = (const float*)d_in[3];
    const float* cb1  = (const float*)d_in[4];
    const float* cw2  = (const float*)d_in[5];
    const float* cb2  = (const float*)d_in[6];
    const float* pw1  = (const float*)d_in[7];
    const float* pb1  = (const float*)d_in[8];
    const float* pw2  = (const float*)d_in[9];
    const float* pb2  = (const float*)d_in[10];
    float* out = (float*)d_out;

    cudaFuncSetAttribute(gemm_hmma, cudaFuncAttributeMaxDynamicSharedMemorySize, SM_TOTAL);

    prolog_kernel<<<224, 512>>>(q, cw1, cb1, pw1, pb1);
    gemm_hmma<<<(M_TOT/128)*2, 256, SM_TOTAL>>>(sent, cw2, cb2);
    for (int s = 0; s < STEPS; s++)
        walk_kernel<<<dim3(Nn/64, Bb), 128>>>(nbrs, s);
    final_kernel<<<M_TOT/8, 256>>>(pw1, pw2, pb2, out);
}